// round 2
// baseline (speedup 1.0000x reference)
#include <cuda_runtime.h>
#include <cstdint>

// N = 16777216, pred: float32 (N,2), target: int64 in reference (device layout
// unknown: int32 or int64 — detected at runtime), output: scalar float mean loss.
// Pure HBM-streaming reduction: 192-268 MB read, 4 B written.

static constexpr int N_ELEMS = 16777216;
static constexpr float INV_N = 1.0f / 16777216.0f;

// 1 if target buffer holds N int32 words; 0 if N int64 values.
__device__ int g_tgt_is_i32;

__global__ void init_kernel(float* out) {
    if (threadIdx.x == 0) {
        out[0] = 0.0f;
        g_tgt_is_i32 = 0;
    }
}

// Scan odd 32-bit words among the first 16384 words (in-bounds for both
// layouts). int64 0/1 values have all-zero high words; int32 random 0/1
// targets have ~half nonzero odd words.
__global__ void detect_kernel(const int* __restrict__ t) {
    int i = blockIdx.x * blockDim.x + threadIdx.x;  // 0..8191
    if (t[2 * i + 1] != 0)
        g_tgt_is_i32 = 1;  // benign race: all writers store 1
}

__device__ __forceinline__ float elem_loss(float p0, float p1, bool z) {
    float a = z ? p0 : p1;   // correct-class prob
    float b = z ? p1 : p0;   // other prob
    float d = 1.0f - a;
    float sq = fmaf(d, d, b * b);
    return sq + (a < b ? 2.0f : 0.0f);
}

__global__ void __launch_bounds__(256) custom_loss_kernel(
    const float4* __restrict__ pred4,   // N/2 float4 (two (p0,p1) rows each)
    const void* __restrict__ tgt,
    float* __restrict__ out,
    int nquads)                          // N/4 groups of 4 elements
{
    const bool i32 = (g_tgt_is_i32 != 0);
    const int4* __restrict__ t32 = (const int4*)tgt;
    const ulonglong2* __restrict__ t64 = (const ulonglong2*)tgt;

    float acc = 0.0f;
    int idx = blockIdx.x * blockDim.x + threadIdx.x;
    int stride = gridDim.x * blockDim.x;

    for (int i = idx; i < nquads; i += stride) {
        float4 pa = __ldg(pred4 + 2 * i);       // elements 4i, 4i+1
        float4 pb = __ldg(pred4 + 2 * i + 1);   // elements 4i+2, 4i+3

        bool z0, z1, z2, z3;
        if (i32) {
            int4 t = __ldg(t32 + i);
            z0 = (t.x == 0); z1 = (t.y == 0); z2 = (t.z == 0); z3 = (t.w == 0);
        } else {
            ulonglong2 ta = __ldg(t64 + 2 * i);
            ulonglong2 tb = __ldg(t64 + 2 * i + 1);
            z0 = (ta.x == 0ULL); z1 = (ta.y == 0ULL);
            z2 = (tb.x == 0ULL); z3 = (tb.y == 0ULL);
        }

        acc += elem_loss(pa.x, pa.y, z0);
        acc += elem_loss(pa.z, pa.w, z1);
        acc += elem_loss(pb.x, pb.y, z2);
        acc += elem_loss(pb.z, pb.w, z3);
    }

    // intra-warp reduce
    #pragma unroll
    for (int o = 16; o > 0; o >>= 1)
        acc += __shfl_xor_sync(0xFFFFFFFFu, acc, o);

    __shared__ float smem[8];  // 256 threads = 8 warps
    int lane = threadIdx.x & 31;
    int warp = threadIdx.x >> 5;
    if (lane == 0) smem[warp] = acc;
    __syncthreads();

    if (warp == 0) {
        acc = (lane < 8) ? smem[lane] : 0.0f;
        #pragma unroll
        for (int o = 4; o > 0; o >>= 1)
            acc += __shfl_xor_sync(0xFFFFFFFFu, acc, o);
        if (lane == 0)
            atomicAdd(out, acc * INV_N);
    }
}

extern "C" void kernel_launch(void* const* d_in, const int* in_sizes, int n_in,
                              void* d_out, int out_size) {
    const float4* pred4 = (const float4*)d_in[0];
    const void* tgt = d_in[1];
    float* out = (float*)d_out;

    init_kernel<<<1, 32>>>(out);
    detect_kernel<<<32, 256>>>((const int*)tgt);

    int nquads = N_ELEMS / 4;  // 4194304
    int blocks = 148 * 16;     // 2368 blocks x 256 threads
    custom_loss_kernel<<<blocks, 256>>>(pred4, tgt, out, nquads);
}